// round 1
// baseline (speedup 1.0000x reference)
#include <cuda_runtime.h>
#include <cstdint>

#define Nn 8192
#define Mm 128
#define EPSf 1e-4f

// Scratch (device globals: allocation-free per harness rules)
static __device__ float  g_E[(size_t)Nn * Nn];   // exp(S), 256 MB
static __device__ float  g_Z[Nn];                // row sums of exp(S)
static __device__ float  g_W[Nn];                // col sums of exp(S)
static __device__ float  g_rZ[Nn];
static __device__ float  g_rW[Nn];
static __device__ double g_loss;

__global__ void zero_kernel() {
    int i = blockIdx.x * blockDim.x + threadIdx.x;
    if (i < Nn) { g_Z[i] = 0.0f; g_W[i] = 0.0f; }
    if (i == 0) g_loss = 0.0;
}

// Pass 1: S tile (64x64) = out2[i0:i0+64,:] * out1[j0:j0+64,:]^T, K=128.
// Writes exp(S) to g_E, accumulates row/col sums into g_Z/g_W.
__global__ __launch_bounds__(256) void pass1_kernel(const float* __restrict__ out1,
                                                    const float* __restrict__ out2) {
    __shared__ float As[64][68];   // k-major: As[k][row], stride 68 keeps 16B align
    __shared__ float Bs[64][68];   // k-major: Bs[k][col]
    __shared__ float red[64][17];

    const int tx  = threadIdx.x;          // 0..15 -> cols
    const int ty  = threadIdx.y;          // 0..15 -> rows
    const int tid = ty * 16 + tx;
    const int i0  = blockIdx.y * 64;
    const int j0  = blockIdx.x * 64;

    float acc[4][4] = {};

    for (int kc = 0; kc < 2; kc++) {
        // Load 64 rows x 64 k-floats of each operand, transposed into smem
        #pragma unroll
        for (int t = 0; t < 4; t++) {
            int idx = tid + t * 256;       // 0..1023
            int row = idx >> 4;
            int k4  = idx & 15;
            float4 a = *(const float4*)&out2[(size_t)(i0 + row) * Mm + kc * 64 + k4 * 4];
            float4 b = *(const float4*)&out1[(size_t)(j0 + row) * Mm + kc * 64 + k4 * 4];
            As[k4*4+0][row] = a.x; As[k4*4+1][row] = a.y;
            As[k4*4+2][row] = a.z; As[k4*4+3][row] = a.w;
            Bs[k4*4+0][row] = b.x; Bs[k4*4+1][row] = b.y;
            Bs[k4*4+2][row] = b.z; Bs[k4*4+3][row] = b.w;
        }
        __syncthreads();

        #pragma unroll 16
        for (int k = 0; k < 64; k++) {
            float4 a = *(const float4*)&As[k][ty * 4];
            float4 b = *(const float4*)&Bs[k][tx * 4];
            float av[4] = {a.x, a.y, a.z, a.w};
            float bv[4] = {b.x, b.y, b.z, b.w};
            #pragma unroll
            for (int r = 0; r < 4; r++)
                #pragma unroll
                for (int c = 0; c < 4; c++)
                    acc[r][c] = fmaf(av[r], bv[c], acc[r][c]);
        }
        __syncthreads();
    }

    // exp, store E, gather per-thread row/col partial sums
    float rowsum[4];
    float colsum[4] = {0.f, 0.f, 0.f, 0.f};
    #pragma unroll
    for (int r = 0; r < 4; r++) {
        float e0 = __expf(acc[r][0]);
        float e1 = __expf(acc[r][1]);
        float e2 = __expf(acc[r][2]);
        float e3 = __expf(acc[r][3]);
        rowsum[r] = (e0 + e1) + (e2 + e3);
        colsum[0] += e0; colsum[1] += e1; colsum[2] += e2; colsum[3] += e3;
        float4 ev = make_float4(e0, e1, e2, e3);
        *(float4*)&g_E[(size_t)(i0 + ty * 4 + r) * Nn + j0 + tx * 4] = ev;
    }

    // Row-sum reduction across tx
    #pragma unroll
    for (int r = 0; r < 4; r++) red[ty * 4 + r][tx] = rowsum[r];
    __syncthreads();
    if (tid < 64) {
        float s = 0.f;
        #pragma unroll
        for (int t = 0; t < 16; t++) s += red[tid][t];
        atomicAdd(&g_Z[i0 + tid], s);
    }
    __syncthreads();

    // Col-sum reduction across ty
    #pragma unroll
    for (int c = 0; c < 4; c++) red[tx * 4 + c][ty] = colsum[c];
    __syncthreads();
    if (tid < 64) {
        float s = 0.f;
        #pragma unroll
        for (int t = 0; t < 16; t++) s += red[tid][t];
        atomicAdd(&g_W[j0 + tid], s);
    }
}

__global__ void recip_kernel() {
    int i = blockIdx.x * blockDim.x + threadIdx.x;
    if (i < Nn) {
        g_rZ[i] = 1.0f / g_Z[i];
        g_rW[i] = 1.0f / g_W[i];
    }
}

// Pass 2: loss = sum -label * (log(E*rZ + eps) + log(E*rW + eps))
__global__ __launch_bounds__(256) void pass2_kernel(const float* __restrict__ label) {
    __shared__ float sred[256];
    const size_t nq = (size_t)Nn * Nn / 4;           // float4 count
    const size_t stride = (size_t)gridDim.x * blockDim.x;
    float acc = 0.f;
    for (size_t q = (size_t)blockIdx.x * blockDim.x + threadIdx.x; q < nq; q += stride) {
        size_t base = q * 4;
        int i = (int)(base >> 13);          // row
        int j = (int)(base & (Nn - 1));     // col (4 consecutive, same row)
        float4 e   = *(const float4*)(g_E + base);
        float4 lab = *(const float4*)(label + base);
        float  rZ  = g_rZ[i];
        float4 rw  = *(const float4*)&g_rW[j];
        acc += lab.x * (__logf(e.x * rZ + EPSf) + __logf(e.x * rw.x + EPSf));
        acc += lab.y * (__logf(e.y * rZ + EPSf) + __logf(e.y * rw.y + EPSf));
        acc += lab.z * (__logf(e.z * rZ + EPSf) + __logf(e.z * rw.z + EPSf));
        acc += lab.w * (__logf(e.w * rZ + EPSf) + __logf(e.w * rw.w + EPSf));
    }
    sred[threadIdx.x] = acc;
    __syncthreads();
    #pragma unroll
    for (int s = 128; s > 0; s >>= 1) {
        if (threadIdx.x < s) sred[threadIdx.x] += sred[threadIdx.x + s];
        __syncthreads();
    }
    if (threadIdx.x == 0) atomicAdd(&g_loss, -(double)sred[0]);
}

__global__ void final_kernel(float* out) {
    out[0] = (float)g_loss;
}

extern "C" void kernel_launch(void* const* d_in, const int* in_sizes, int n_in,
                              void* d_out, int out_size) {
    const float* out1  = (const float*)d_in[0];   // [8192,128]
    const float* out2  = (const float*)d_in[1];   // [8192,128]
    const float* label = (const float*)d_in[2];   // [8192,8192]

    zero_kernel<<<32, 256>>>();
    dim3 grid(Nn / 64, Nn / 64);
    dim3 block(16, 16);
    pass1_kernel<<<grid, block>>>(out1, out2);
    recip_kernel<<<32, 256>>>();
    pass2_kernel<<<8192, 256>>>(label);
    final_kernel<<<1, 1>>>((float*)d_out);
}

// round 3
// speedup vs baseline: 1.6673x; 1.6673x over previous
#include <cuda_runtime.h>
#include <cuda_bf16.h>
#include <cstdint>

#define Nn 8192
#define Mm 128
#define EPSf 1e-4f
#define LDA 136   // bf16 elements per smem tile row (128 + 8 pad -> conflict-free ldmatrix)

// ---------------- device scratch (allocation-free) ----------------
static __device__ float  g_E[(size_t)Nn * Nn];   // exp(S), 256 MB
static __device__ float  g_Z[Nn];                // row sums of exp(S)
static __device__ float  g_W[Nn];                // col sums of exp(S)
static __device__ float  g_rZ[Nn];
static __device__ float  g_rW[Nn];
static __device__ double g_loss;

__device__ __forceinline__ uint32_t smem_u32(const void* p) {
    uint32_t a;
    asm("{ .reg .u64 t; cvta.to.shared.u64 t, %1; cvt.u32.u64 %0, t; }" : "=r"(a) : "l"(p));
    return a;
}

__device__ __forceinline__ void ldmx4(uint32_t* r, uint32_t addr) {
    asm volatile("ldmatrix.sync.aligned.m8n8.x4.shared.b16 {%0,%1,%2,%3}, [%4];"
                 : "=r"(r[0]), "=r"(r[1]), "=r"(r[2]), "=r"(r[3]) : "r"(addr));
}

__device__ __forceinline__ void mma16816(float* c, const uint32_t* a, uint32_t b0, uint32_t b1) {
    asm volatile(
        "mma.sync.aligned.m16n8k16.row.col.f32.bf16.bf16.f32 "
        "{%0,%1,%2,%3}, {%4,%5,%6,%7}, {%8,%9}, {%0,%1,%2,%3};"
        : "+f"(c[0]), "+f"(c[1]), "+f"(c[2]), "+f"(c[3])
        : "r"(a[0]), "r"(a[1]), "r"(a[2]), "r"(a[3]), "r"(b0), "r"(b1));
}

__global__ void zero_kernel() {
    int i = blockIdx.x * blockDim.x + threadIdx.x;
    if (i < Nn) { g_Z[i] = 0.0f; g_W[i] = 0.0f; }
    if (i == 0) g_loss = 0.0;
}

// tiles: A_hi, A_lo, B_hi, B_lo each 128 x LDA bf16 (34816 B) -> 139264 B total
#define TILE_ELEMS (128 * LDA)
#define SMEM_BYTES (4 * TILE_ELEMS * 2)

// ---------------- Pass 1: mma.sync bf16x3 GEMM + exp + row/col sums + E store --------
__global__ __launch_bounds__(256, 1) void pass1_mma(const float* __restrict__ out1,
                                                    const float* __restrict__ out2) {
    extern __shared__ char sm[];
    __nv_bfloat16* Ah = (__nv_bfloat16*)sm;
    __nv_bfloat16* Al = Ah + TILE_ELEMS;
    __nv_bfloat16* Bh = Al + TILE_ELEMS;
    __nv_bfloat16* Bl = Bh + TILE_ELEMS;
    float* sE = (float*)sm;                      // epilogue staging overlays tiles

    const int tid  = threadIdx.x;
    const int wid  = tid >> 5;
    const int lane = tid & 31;
    const int i0 = blockIdx.y * 128;   // rows from out2
    const int j0 = blockIdx.x * 128;   // cols from out1

    // ---- load fp32, split into bf16 hi/lo, store to padded smem tiles ----
    for (int t = tid; t < 4096; t += 256) {
        int row = t >> 5;          // 0..127
        int k   = (t & 31) * 4;    // 0..124
        float4 a = *(const float4*)&out2[(size_t)(i0 + row) * Mm + k];
        float4 b = *(const float4*)&out1[(size_t)(j0 + row) * Mm + k];

        __nv_bfloat162 ah0 = __float22bfloat162_rn(make_float2(a.x, a.y));
        __nv_bfloat162 ah1 = __float22bfloat162_rn(make_float2(a.z, a.w));
        float2 af0 = __bfloat1622float2(ah0), af1 = __bfloat1622float2(ah1);
        __nv_bfloat162 al0 = __float22bfloat162_rn(make_float2(a.x - af0.x, a.y - af0.y));
        __nv_bfloat162 al1 = __float22bfloat162_rn(make_float2(a.z - af1.x, a.w - af1.y));

        __nv_bfloat162 bh0 = __float22bfloat162_rn(make_float2(b.x, b.y));
        __nv_bfloat162 bh1 = __float22bfloat162_rn(make_float2(b.z, b.w));
        float2 bf0 = __bfloat1622float2(bh0), bf1 = __bfloat1622float2(bh1);
        __nv_bfloat162 bl0 = __float22bfloat162_rn(make_float2(b.x - bf0.x, b.y - bf0.y));
        __nv_bfloat162 bl1 = __float22bfloat162_rn(make_float2(b.z - bf1.x, b.w - bf1.y));

        int e = row * LDA + k;
        *(uint2*)&Ah[e] = make_uint2(*(uint32_t*)&ah0, *(uint32_t*)&ah1);
        *(uint2*)&Al[e] = make_uint2(*(uint32_t*)&al0, *(uint32_t*)&al1);
        *(uint2*)&Bh[e] = make_uint2(*(uint32_t*)&bh0, *(uint32_t*)&bh1);
        *(uint2*)&Bl[e] = make_uint2(*(uint32_t*)&bl0, *(uint32_t*)&bl1);
    }
    __syncthreads();

    // ---- warp-tiled MMA: warp (wm, wn) computes rows [m0,m0+32) x cols [n0,n0+64) ----
    const int wm = wid & 3, wn = wid >> 2;
    const int m0 = wm * 32, n0 = wn * 64;

    float c[2][8][4];
    #pragma unroll
    for (int mt = 0; mt < 2; mt++)
        #pragma unroll
        for (int nt = 0; nt < 8; nt++)
            #pragma unroll
            for (int q = 0; q < 4; q++) c[mt][nt][q] = 0.f;

    // ldmatrix per-lane source rows/k-offsets
    const int aro = (lane & 7) + ((lane >> 3) & 1) * 8;
    const int ako = ((lane >> 4) & 1) * 8;
    const int bro = (lane & 7) + ((lane >> 4) & 1) * 8;
    const int bko = ((lane >> 3) & 1) * 8;

    const uint32_t sAh = smem_u32(Ah), sAl = smem_u32(Al);
    const uint32_t sBh = smem_u32(Bh), sBl = smem_u32(Bl);
    const uint32_t aoff = (uint32_t)(((m0 + aro) * LDA + ako) * 2);
    uint32_t boff[4];
    #pragma unroll
    for (int p = 0; p < 4; p++)
        boff[p] = (uint32_t)(((n0 + p * 16 + bro) * LDA + bko) * 2);

    #pragma unroll
    for (int kk = 0; kk < 8; kk++) {
        const uint32_t kb = (uint32_t)(kk * 32);   // 16 bf16 = 32 B
        uint32_t ah[2][4], al[2][4], bh[4][4], bl[4][4];
        #pragma unroll
        for (int mt = 0; mt < 2; mt++) {
            ldmx4(ah[mt], sAh + aoff + (uint32_t)(mt * 16 * LDA * 2) + kb);
            ldmx4(al[mt], sAl + aoff + (uint32_t)(mt * 16 * LDA * 2) + kb);
        }
        #pragma unroll
        for (int p = 0; p < 4; p++) {
            ldmx4(bh[p], sBh + boff[p] + kb);
            ldmx4(bl[p], sBl + boff[p] + kb);
        }
        #pragma unroll
        for (int mt = 0; mt < 2; mt++)
            #pragma unroll
            for (int nt = 0; nt < 8; nt++) {
                const int p = nt >> 1, r = (nt & 1) * 2;
                mma16816(c[mt][nt], ah[mt], bh[p][r], bh[p][r + 1]);
                mma16816(c[mt][nt], ah[mt], bl[p][r], bl[p][r + 1]);
                mma16816(c[mt][nt], al[mt], bh[p][r], bh[p][r + 1]);
            }
    }

    // ---- epilogue: exp, row sums (shuffle), stage to smem, col sums, coalesced store ----
    float rsum[2][2] = {{0.f, 0.f}, {0.f, 0.f}};
    #pragma unroll
    for (int mt = 0; mt < 2; mt++)
        #pragma unroll
        for (int nt = 0; nt < 8; nt++) {
            #pragma unroll
            for (int q = 0; q < 4; q++) c[mt][nt][q] = __expf(c[mt][nt][q]);
            rsum[mt][0] += c[mt][nt][0] + c[mt][nt][1];
            rsum[mt][1] += c[mt][nt][2] + c[mt][nt][3];
        }
    #pragma unroll
    for (int mt = 0; mt < 2; mt++)
        #pragma unroll
        for (int h = 0; h < 2; h++) {
            float s = rsum[mt][h];
            s += __shfl_xor_sync(0xFFFFFFFF, s, 1);
            s += __shfl_xor_sync(0xFFFFFFFF, s, 2);
            if ((lane & 3) == 0)
                atomicAdd(&g_Z[i0 + m0 + mt * 16 + h * 8 + (lane >> 2)], s);
        }

    __syncthreads();   // all warps done reading tiles before sE overwrite

    #pragma unroll
    for (int mt = 0; mt < 2; mt++)
        #pragma unroll
        for (int nt = 0; nt < 8; nt++) {
            int row = m0 + mt * 16 + (lane >> 2);
            int col = n0 + nt * 8 + (lane & 3) * 2;
            *(float2*)&sE[(size_t)row * 132 + col]       = make_float2(c[mt][nt][0], c[mt][nt][1]);
            *(float2*)&sE[(size_t)(row + 8) * 132 + col] = make_float2(c[mt][nt][2], c[mt][nt][3]);
        }
    __syncthreads();

    {   // column sums
        int cc = tid & 127;
        int rh = tid >> 7;
        float s = 0.f;
        #pragma unroll 8
        for (int r = rh * 64; r < rh * 64 + 64; r++) s += sE[(size_t)r * 132 + cc];
        atomicAdd(&g_W[j0 + cc], s);
    }

    #pragma unroll
    for (int it = 0; it < 16; it++) {   // coalesced E store
        int r = wid * 16 + it;
        float4 v = *(float4*)&sE[(size_t)r * 132 + lane * 4];
        *(float4*)&g_E[(size_t)(i0 + r) * Nn + j0 + lane * 4] = v;
    }
}

__global__ void recip_kernel() {
    int i = blockIdx.x * blockDim.x + threadIdx.x;
    if (i < Nn) { g_rZ[i] = 1.0f / g_Z[i]; g_rW[i] = 1.0f / g_W[i]; }
}

// ---------------- Pass 2: loss reduction ----------------
__global__ __launch_bounds__(256) void pass2_kernel(const float* __restrict__ label) {
    __shared__ float sred[256];
    const size_t nq = (size_t)Nn * Nn / 4;
    const size_t stride = (size_t)gridDim.x * blockDim.x;
    float acc = 0.f;
    for (size_t q = (size_t)blockIdx.x * blockDim.x + threadIdx.x; q < nq; q += stride) {
        size_t base = q * 4;
        int i = (int)(base >> 13);
        int j = (int)(base & (Nn - 1));
        float4 e   = *(const float4*)(g_E + base);
        float4 lab = *(const float4*)(label + base);
        float  rZ  = g_rZ[i];
        float4 rw  = *(const float4*)&g_rW[j];
        acc += lab.x * (__logf(e.x * rZ + EPSf) + __logf(e.x * rw.x + EPSf));
        acc += lab.y * (__logf(e.y * rZ + EPSf) + __logf(e.y * rw.y + EPSf));
        acc += lab.z * (__logf(e.z * rZ + EPSf) + __logf(e.z * rw.z + EPSf));
        acc += lab.w * (__logf(e.w * rZ + EPSf) + __logf(e.w * rw.w + EPSf));
    }
    sred[threadIdx.x] = acc;
    __syncthreads();
    #pragma unroll
    for (int s = 128; s > 0; s >>= 1) {
        if (threadIdx.x < s) sred[threadIdx.x] += sred[threadIdx.x + s];
        __syncthreads();
    }
    if (threadIdx.x == 0) atomicAdd(&g_loss, -(double)sred[0]);
}

__global__ void final_kernel(float* out) { out[0] = (float)g_loss; }

extern "C" void kernel_launch(void* const* d_in, const int* in_sizes, int n_in,
                              void* d_out, int out_size) {
    const float* out1  = (const float*)d_in[0];
    const float* out2  = (const float*)d_in[1];
    const float* label = (const float*)d_in[2];

    cudaFuncSetAttribute(pass1_mma, cudaFuncAttributeMaxDynamicSharedMemorySize, SMEM_BYTES);

    zero_kernel<<<32, 256>>>();
    dim3 grid(Nn / 128, Nn / 128);
    pass1_mma<<<grid, 256, SMEM_BYTES>>>(out1, out2);
    recip_kernel<<<32, 256>>>();
    pass2_kernel<<<8192, 256>>>(label);
    final_kernel<<<1, 1>>>((float*)d_out);
}

// round 4
// speedup vs baseline: 2.4618x; 1.4765x over previous
#include <cuda_runtime.h>
#include <cuda_fp16.h>
#include <cuda_bf16.h>
#include <cstdint>

#define Nn 8192
#define Mm 128
#define EPSf 1e-4f
#define LDA 136   // bf16 elems per smem tile row (128 + 8 pad -> conflict-free ldmatrix)

// ---------------- device scratch (allocation-free) ----------------
static __device__ __half g_S[(size_t)Nn * Nn];   // scores fp16, 128 MB
static __device__ float  g_Z[Nn];
static __device__ float  g_W[Nn];
static __device__ float  g_rZ[Nn];
static __device__ float  g_rW[Nn];
static __device__ double g_loss;

__device__ __forceinline__ uint32_t smem_u32(const void* p) {
    uint32_t a;
    asm("{ .reg .u64 t; cvta.to.shared.u64 t, %1; cvt.u32.u64 %0, t; }" : "=r"(a) : "l"(p));
    return a;
}
__device__ __forceinline__ void ldmx4(uint32_t* r, uint32_t addr) {
    asm volatile("ldmatrix.sync.aligned.m8n8.x4.shared.b16 {%0,%1,%2,%3}, [%4];"
                 : "=r"(r[0]), "=r"(r[1]), "=r"(r[2]), "=r"(r[3]) : "r"(addr));
}
__device__ __forceinline__ void mma16816(float* c, const uint32_t* a, uint32_t b0, uint32_t b1) {
    asm volatile(
        "mma.sync.aligned.m16n8k16.row.col.f32.bf16.bf16.f32 "
        "{%0,%1,%2,%3}, {%4,%5,%6,%7}, {%8,%9}, {%0,%1,%2,%3};"
        : "+f"(c[0]), "+f"(c[1]), "+f"(c[2]), "+f"(c[3])
        : "r"(a[0]), "r"(a[1]), "r"(a[2]), "r"(a[3]), "r"(b0), "r"(b1));
}

__global__ void zero_kernel() {
    int i = blockIdx.x * blockDim.x + threadIdx.x;
    if (i < Nn) { g_Z[i] = 0.0f; g_W[i] = 0.0f; }
    if (i == 0) g_loss = 0.0;
}

// smem: Ah,Al: 128 x LDA bf16 ; Bh,Bl: 64 x LDA bf16  -> 104448 B (2 CTAs/SM)
#define A_ELEMS (128 * LDA)
#define B_ELEMS (64 * LDA)
#define SMEM_BYTES ((2 * A_ELEMS + 2 * B_ELEMS) * 2)

// ---------------- Pass 1: CTA tile 128(M) x 64(N), bf16x3 mma.sync ----------------
__global__ __launch_bounds__(256, 2) void pass1_mma(const float* __restrict__ out1,
                                                    const float* __restrict__ out2) {
    extern __shared__ char sm[];
    __nv_bfloat16* Ah = (__nv_bfloat16*)sm;
    __nv_bfloat16* Al = Ah + A_ELEMS;
    __nv_bfloat16* Bh = Al + A_ELEMS;
    __nv_bfloat16* Bl = Bh + B_ELEMS;
    uint32_t* stage = (uint32_t*)sm;   // epilogue staging (128 x 36 words) overlays tiles

    const int tid  = threadIdx.x;
    const int wid  = tid >> 5;
    const int lane = tid & 31;
    const int i0 = blockIdx.y * 128;   // rows (out2)
    const int j0 = blockIdx.x * 64;    // cols (out1)

    // ---- load fp32 -> bf16 hi/lo split into padded smem tiles ----
    #pragma unroll 4
    for (int t = tid; t < 4096; t += 256) {           // A: 128 rows x 32 float4
        int row = t >> 5, k = (t & 31) * 4;
        float4 a = *(const float4*)&out2[(size_t)(i0 + row) * Mm + k];
        __nv_bfloat162 h0 = __float22bfloat162_rn(make_float2(a.x, a.y));
        __nv_bfloat162 h1 = __float22bfloat162_rn(make_float2(a.z, a.w));
        float2 f0 = __bfloat1622float2(h0), f1 = __bfloat1622float2(h1);
        __nv_bfloat162 l0 = __float22bfloat162_rn(make_float2(a.x - f0.x, a.y - f0.y));
        __nv_bfloat162 l1 = __float22bfloat162_rn(make_float2(a.z - f1.x, a.w - f1.y));
        int e = row * LDA + k;
        *(uint2*)&Ah[e] = make_uint2(*(uint32_t*)&h0, *(uint32_t*)&h1);
        *(uint2*)&Al[e] = make_uint2(*(uint32_t*)&l0, *(uint32_t*)&l1);
    }
    #pragma unroll 2
    for (int t = tid; t < 2048; t += 256) {           // B: 64 rows x 32 float4
        int row = t >> 5, k = (t & 31) * 4;
        float4 b = *(const float4*)&out1[(size_t)(j0 + row) * Mm + k];
        __nv_bfloat162 h0 = __float22bfloat162_rn(make_float2(b.x, b.y));
        __nv_bfloat162 h1 = __float22bfloat162_rn(make_float2(b.z, b.w));
        float2 f0 = __bfloat1622float2(h0), f1 = __bfloat1622float2(h1);
        __nv_bfloat162 l0 = __float22bfloat162_rn(make_float2(b.x - f0.x, b.y - f0.y));
        __nv_bfloat162 l1 = __float22bfloat162_rn(make_float2(b.z - f1.x, b.w - f1.y));
        int e = row * LDA + k;
        *(uint2*)&Bh[e] = make_uint2(*(uint32_t*)&h0, *(uint32_t*)&h1);
        *(uint2*)&Bl[e] = make_uint2(*(uint32_t*)&l0, *(uint32_t*)&l1);
    }
    __syncthreads();

    // ---- warp tiling: 8 warps as 4(m) x 2(n); warp tile 32 x 32 ----
    const int wm = wid & 3, wn = wid >> 2;
    const int m0w = wm * 32, n0w = wn * 32;

    float c[2][4][4];
    #pragma unroll
    for (int mt = 0; mt < 2; mt++)
        #pragma unroll
        for (int nt = 0; nt < 4; nt++)
            #pragma unroll
            for (int q = 0; q < 4; q++) c[mt][nt][q] = 0.f;

    const int aro = (lane & 7) + ((lane >> 3) & 1) * 8;
    const int ako = ((lane >> 4) & 1) * 8;
    const int bro = (lane & 7) + ((lane >> 4) & 1) * 8;
    const int bko = ((lane >> 3) & 1) * 8;

    const uint32_t sAh = smem_u32(Ah), sAl = smem_u32(Al);
    const uint32_t sBh = smem_u32(Bh), sBl = smem_u32(Bl);
    const uint32_t aoff = (uint32_t)(((m0w + aro) * LDA + ako) * 2);
    uint32_t boff[2];
    #pragma unroll
    for (int p = 0; p < 2; p++)
        boff[p] = (uint32_t)(((n0w + p * 16 + bro) * LDA + bko) * 2);

    #pragma unroll
    for (int kk = 0; kk < 8; kk++) {
        const uint32_t kb = (uint32_t)(kk * 32);
        uint32_t ah[2][4], al[2][4], bh[2][4], bl[2][4];
        #pragma unroll
        for (int mt = 0; mt < 2; mt++) {
            ldmx4(ah[mt], sAh + aoff + (uint32_t)(mt * 16 * LDA * 2) + kb);
            ldmx4(al[mt], sAl + aoff + (uint32_t)(mt * 16 * LDA * 2) + kb);
        }
        #pragma unroll
        for (int p = 0; p < 2; p++) {
            ldmx4(bh[p], sBh + boff[p] + kb);
            ldmx4(bl[p], sBl + boff[p] + kb);
        }
        #pragma unroll
        for (int mt = 0; mt < 2; mt++)
            #pragma unroll
            for (int nt = 0; nt < 4; nt++) {
                const int p = nt >> 1, r = (nt & 1) * 2;
                mma16816(c[mt][nt], ah[mt], bh[p][r], bh[p][r + 1]);
                mma16816(c[mt][nt], ah[mt], bl[p][r], bl[p][r + 1]);
                mma16816(c[mt][nt], al[mt], bh[p][r], bh[p][r + 1]);
            }
    }

    __syncthreads();   // tiles dead; staging may overwrite

    // ---- stage fp16 scores into smem (stride 36 words = 72 halves) ----
    #pragma unroll
    for (int mt = 0; mt < 2; mt++)
        #pragma unroll
        for (int nt = 0; nt < 4; nt++) {
            int row = m0w + mt * 16 + (lane >> 2);
            int cw  = (n0w + nt * 8 + (lane & 3) * 2) >> 1;   // word index in row
            __half2 p0 = __float22half2_rn(make_float2(c[mt][nt][0], c[mt][nt][1]));
            __half2 p1 = __float22half2_rn(make_float2(c[mt][nt][2], c[mt][nt][3]));
            stage[(size_t)row * 36 + cw]       = *(uint32_t*)&p0;
            stage[(size_t)(row + 8) * 36 + cw] = *(uint32_t*)&p1;
        }

    // ---- exp in registers; row sums + col sums via shuffles ----
    #pragma unroll
    for (int mt = 0; mt < 2; mt++)
        #pragma unroll
        for (int nt = 0; nt < 4; nt++)
            #pragma unroll
            for (int q = 0; q < 4; q++) c[mt][nt][q] = __expf(c[mt][nt][q]);

    #pragma unroll
    for (int mt = 0; mt < 2; mt++) {
        float r0 = 0.f, r1 = 0.f;
        #pragma unroll
        for (int nt = 0; nt < 4; nt++) {
            r0 += c[mt][nt][0] + c[mt][nt][1];
            r1 += c[mt][nt][2] + c[mt][nt][3];
        }
        r0 += __shfl_xor_sync(0xFFFFFFFF, r0, 1);
        r0 += __shfl_xor_sync(0xFFFFFFFF, r0, 2);
        r1 += __shfl_xor_sync(0xFFFFFFFF, r1, 1);
        r1 += __shfl_xor_sync(0xFFFFFFFF, r1, 2);
        if ((lane & 3) == 0) {
            atomicAdd(&g_Z[i0 + m0w + mt * 16 + (lane >> 2)], r0);
            atomicAdd(&g_Z[i0 + m0w + mt * 16 + 8 + (lane >> 2)], r1);
        }
    }
    #pragma unroll
    for (int nt = 0; nt < 4; nt++) {
        float v0 = c[0][nt][0] + c[0][nt][2] + c[1][nt][0] + c[1][nt][2];
        float v1 = c[0][nt][1] + c[0][nt][3] + c[1][nt][1] + c[1][nt][3];
        v0 += __shfl_xor_sync(0xFFFFFFFF, v0, 4);
        v0 += __shfl_xor_sync(0xFFFFFFFF, v0, 8);
        v0 += __shfl_xor_sync(0xFFFFFFFF, v0, 16);
        v1 += __shfl_xor_sync(0xFFFFFFFF, v1, 4);
        v1 += __shfl_xor_sync(0xFFFFFFFF, v1, 8);
        v1 += __shfl_xor_sync(0xFFFFFFFF, v1, 16);
        if (lane < 4) {
            int col = j0 + n0w + nt * 8 + lane * 2;
            atomicAdd(&g_W[col], v0);
            atomicAdd(&g_W[col + 1], v1);
        }
    }
    __syncthreads();

    // ---- coalesced fp16 store: each warp 16 rows, 128B per row ----
    uint32_t* gS32 = (uint32_t*)g_S;
    #pragma unroll
    for (int it = 0; it < 16; it++) {
        int r = wid * 16 + it;
        gS32[(size_t)(i0 + r) * (Nn / 2) + (j0 >> 1) + lane] = stage[(size_t)r * 36 + lane];
    }
}

__global__ void recip_kernel() {
    int i = blockIdx.x * blockDim.x + threadIdx.x;
    if (i < Nn) { g_rZ[i] = 1.0f / g_Z[i]; g_rW[i] = 1.0f / g_W[i]; }
}

// ---------------- Pass 2: loss from fp16 scores ----------------
__global__ __launch_bounds__(256) void pass2_kernel(const float* __restrict__ label) {
    __shared__ float sred[256];
    const size_t nq = (size_t)Nn * Nn / 8;            // 8 elems per iter
    const size_t stride = (size_t)gridDim.x * blockDim.x;
    float acc = 0.f;
    for (size_t q = (size_t)blockIdx.x * blockDim.x + threadIdx.x; q < nq; q += stride) {
        size_t base = q * 8;
        int i = (int)(base >> 13);
        int j = (int)(base & (Nn - 1));
        uint4 sv = *(const uint4*)((const uint32_t*)g_S + (base >> 1));
        float4 l0 = *(const float4*)(label + base);
        float4 l1 = *(const float4*)(label + base + 4);
        float  rZ = g_rZ[i];
        float4 w0 = *(const float4*)&g_rW[j];
        float4 w1 = *(const float4*)&g_rW[j + 4];

        float2 s0 = __half22float2(*(__half2*)&sv.x);
        float2 s1 = __half22float2(*(__half2*)&sv.y);
        float2 s2 = __half22float2(*(__half2*)&sv.z);
        float2 s3 = __half22float2(*(__half2*)&sv.w);

        float e0 = __expf(s0.x), e1 = __expf(s0.y), e2 = __expf(s1.x), e3 = __expf(s1.y);
        float e4 = __expf(s2.x), e5 = __expf(s2.y), e6 = __expf(s3.x), e7 = __expf(s3.y);

        acc += l0.x * (__logf(e0 * rZ + EPSf) + __logf(e0 * w0.x + EPSf));
        acc += l0.y * (__logf(e1 * rZ + EPSf) + __logf(e1 * w0.y + EPSf));
        acc += l0.z * (__logf(e2 * rZ + EPSf) + __logf(e2 * w0.z + EPSf));
        acc += l0.w * (__logf(e3 * rZ + EPSf) + __logf(e3 * w0.w + EPSf));
        acc += l1.x * (__logf(e4 * rZ + EPSf) + __logf(e4 * w1.x + EPSf));
        acc += l1.y * (__logf(e5 * rZ + EPSf) + __logf(e5 * w1.y + EPSf));
        acc += l1.z * (__logf(e6 * rZ + EPSf) + __logf(e6 * w1.z + EPSf));
        acc += l1.w * (__logf(e7 * rZ + EPSf) + __logf(e7 * w1.w + EPSf));
    }
    sred[threadIdx.x] = acc;
    __syncthreads();
    #pragma unroll
    for (int s = 128; s > 0; s >>= 1) {
        if (threadIdx.x < s) sred[threadIdx.x] += sred[threadIdx.x + s];
        __syncthreads();
    }
    if (threadIdx.x == 0) atomicAdd(&g_loss, -(double)sred[0]);
}

__global__ void final_kernel(float* out) { out[0] = (float)g_loss; }

extern "C" void kernel_launch(void* const* d_in, const int* in_sizes, int n_in,
                              void* d_out, int out_size) {
    const float* out1  = (const float*)d_in[0];
    const float* out2  = (const float*)d_in[1];
    const float* label = (const float*)d_in[2];

    cudaFuncSetAttribute(pass1_mma, cudaFuncAttributeMaxDynamicSharedMemorySize, SMEM_BYTES);

    zero_kernel<<<32, 256>>>();
    dim3 grid(Nn / 64, Nn / 128);
    pass1_mma<<<grid, 256, SMEM_BYTES>>>(out1, out2);
    recip_kernel<<<32, 256>>>();
    pass2_kernel<<<8192, 256>>>(label);
    final_kernel<<<1, 1>>>((float*)d_out);
}

// round 5
// speedup vs baseline: 3.6788x; 1.4944x over previous
#include <cuda_runtime.h>
#include <cuda_fp16.h>
#include <cstdint>

#define Nn 8192
#define Mm 128
#define EPSf 1e-4f
#define LDA 136   // fp16 elems per smem tile row (128 + 8 pad -> conflict-free ldmatrix)

// ---------------- device scratch (allocation-free) ----------------
static __device__ __half g_S[(size_t)Nn * Nn];   // scores fp16, 128 MB
static __device__ float  g_Z[Nn];
static __device__ float  g_W[Nn];
static __device__ float  g_rZ[Nn];
static __device__ float  g_rW[Nn];
static __device__ double g_loss;

__device__ __forceinline__ uint32_t smem_u32(const void* p) {
    uint32_t a;
    asm("{ .reg .u64 t; cvta.to.shared.u64 t, %1; cvt.u32.u64 %0, t; }" : "=r"(a) : "l"(p));
    return a;
}
__device__ __forceinline__ void ldmx4(uint32_t* r, uint32_t addr) {
    asm volatile("ldmatrix.sync.aligned.m8n8.x4.shared.b16 {%0,%1,%2,%3}, [%4];"
                 : "=r"(r[0]), "=r"(r[1]), "=r"(r[2]), "=r"(r[3]) : "r"(addr));
}
__device__ __forceinline__ void mma16816(float* c, const uint32_t* a, uint32_t b0, uint32_t b1) {
    asm volatile(
        "mma.sync.aligned.m16n8k16.row.col.f32.f16.f16.f32 "
        "{%0,%1,%2,%3}, {%4,%5,%6,%7}, {%8,%9}, {%0,%1,%2,%3};"
        : "+f"(c[0]), "+f"(c[1]), "+f"(c[2]), "+f"(c[3])
        : "r"(a[0]), "r"(a[1]), "r"(a[2]), "r"(a[3]), "r"(b0), "r"(b1));
}

__global__ void zero_kernel() {
    int i = blockIdx.x * blockDim.x + threadIdx.x;
    if (i < Nn) { g_Z[i] = 0.0f; g_W[i] = 0.0f; }
    if (i == 0) g_loss = 0.0;
}

// smem: A: 128 x LDA fp16, B: 128 x LDA fp16 -> 69632 B (2 CTAs/SM)
#define T_ELEMS (128 * LDA)
#define SMEM_BYTES (2 * T_ELEMS * 2)

// ---------------- Pass 1: CTA tile 128 x 128, single fp16 mma.sync ----------------
__global__ __launch_bounds__(256, 2) void pass1_mma(const float* __restrict__ out1,
                                                    const float* __restrict__ out2) {
    extern __shared__ char sm[];
    __half* At = (__half*)sm;
    __half* Bt = At + T_ELEMS;
    uint32_t* stage = (uint32_t*)sm;   // epilogue staging (128 x 68 words) overlays tiles

    const int tid  = threadIdx.x;
    const int wid  = tid >> 5;
    const int lane = tid & 31;
    const int i0 = blockIdx.y * 128;   // rows (out2)
    const int j0 = blockIdx.x * 128;   // cols (out1)

    // ---- load fp32 -> fp16 into padded smem tiles ----
    #pragma unroll 4
    for (int t = tid; t < 4096; t += 256) {
        int row = t >> 5, k = (t & 31) * 4;
        float4 a = *(const float4*)&out2[(size_t)(i0 + row) * Mm + k];
        float4 b = *(const float4*)&out1[(size_t)(j0 + row) * Mm + k];
        __half2 a0 = __float22half2_rn(make_float2(a.x, a.y));
        __half2 a1 = __float22half2_rn(make_float2(a.z, a.w));
        __half2 b0 = __float22half2_rn(make_float2(b.x, b.y));
        __half2 b1 = __float22half2_rn(make_float2(b.z, b.w));
        int e = row * LDA + k;
        *(uint2*)&At[e] = make_uint2(*(uint32_t*)&a0, *(uint32_t*)&a1);
        *(uint2*)&Bt[e] = make_uint2(*(uint32_t*)&b0, *(uint32_t*)&b1);
    }
    __syncthreads();

    // ---- warp tiling: 8 warps as 4(m) x 2(n); warp tile 32 x 64 ----
    const int wm = wid & 3, wn = wid >> 2;
    const int m0w = wm * 32, n0w = wn * 64;

    float c[2][8][4];
    #pragma unroll
    for (int mt = 0; mt < 2; mt++)
        #pragma unroll
        for (int nt = 0; nt < 8; nt++)
            #pragma unroll
            for (int q = 0; q < 4; q++) c[mt][nt][q] = 0.f;

    const int aro = (lane & 7) + ((lane >> 3) & 1) * 8;
    const int ako = ((lane >> 4) & 1) * 8;
    const int bro = (lane & 7) + ((lane >> 4) & 1) * 8;
    const int bko = ((lane >> 3) & 1) * 8;

    const uint32_t sA = smem_u32(At), sB = smem_u32(Bt);
    const uint32_t aoff = (uint32_t)(((m0w + aro) * LDA + ako) * 2);
    uint32_t boff[4];
    #pragma unroll
    for (int p = 0; p < 4; p++)
        boff[p] = (uint32_t)(((n0w + p * 16 + bro) * LDA + bko) * 2);

    #pragma unroll
    for (int kk = 0; kk < 8; kk++) {
        const uint32_t kb = (uint32_t)(kk * 32);   // 16 fp16 = 32 B
        uint32_t av[2][4], bv[4][4];
        #pragma unroll
        for (int mt = 0; mt < 2; mt++)
            ldmx4(av[mt], sA + aoff + (uint32_t)(mt * 16 * LDA * 2) + kb);
        #pragma unroll
        for (int p = 0; p < 4; p++)
            ldmx4(bv[p], sB + boff[p] + kb);
        #pragma unroll
        for (int mt = 0; mt < 2; mt++)
            #pragma unroll
            for (int nt = 0; nt < 8; nt++) {
                const int p = nt >> 1, r = (nt & 1) * 2;
                mma16816(c[mt][nt], av[mt], bv[p][r], bv[p][r + 1]);
            }
    }

    __syncthreads();   // tiles dead; staging may overwrite

    // ---- stage fp16 scores into smem (row stride 68 words -> conflict-free) ----
    #pragma unroll
    for (int mt = 0; mt < 2; mt++)
        #pragma unroll
        for (int nt = 0; nt < 8; nt++) {
            int row = m0w + mt * 16 + (lane >> 2);
            int cw  = (n0w + nt * 8 + (lane & 3) * 2) >> 1;
            __half2 p0 = __float22half2_rn(make_float2(c[mt][nt][0], c[mt][nt][1]));
            __half2 p1 = __float22half2_rn(make_float2(c[mt][nt][2], c[mt][nt][3]));
            stage[(size_t)row * 68 + cw]       = *(uint32_t*)&p0;
            stage[(size_t)(row + 8) * 68 + cw] = *(uint32_t*)&p1;
        }

    // ---- exp in registers; row + col sums via shuffles ----
    #pragma unroll
    for (int mt = 0; mt < 2; mt++)
        #pragma unroll
        for (int nt = 0; nt < 8; nt++)
            #pragma unroll
            for (int q = 0; q < 4; q++) c[mt][nt][q] = __expf(c[mt][nt][q]);

    #pragma unroll
    for (int mt = 0; mt < 2; mt++) {
        float r0 = 0.f, r1 = 0.f;
        #pragma unroll
        for (int nt = 0; nt < 8; nt++) {
            r0 += c[mt][nt][0] + c[mt][nt][1];
            r1 += c[mt][nt][2] + c[mt][nt][3];
        }
        r0 += __shfl_xor_sync(0xFFFFFFFF, r0, 1);
        r0 += __shfl_xor_sync(0xFFFFFFFF, r0, 2);
        r1 += __shfl_xor_sync(0xFFFFFFFF, r1, 1);
        r1 += __shfl_xor_sync(0xFFFFFFFF, r1, 2);
        if ((lane & 3) == 0) {
            atomicAdd(&g_Z[i0 + m0w + mt * 16 + (lane >> 2)], r0);
            atomicAdd(&g_Z[i0 + m0w + mt * 16 + 8 + (lane >> 2)], r1);
        }
    }
    #pragma unroll
    for (int nt = 0; nt < 8; nt++) {
        float v0 = c[0][nt][0] + c[0][nt][2] + c[1][nt][0] + c[1][nt][2];
        float v1 = c[0][nt][1] + c[0][nt][3] + c[1][nt][1] + c[1][nt][3];
        v0 += __shfl_xor_sync(0xFFFFFFFF, v0, 4);
        v0 += __shfl_xor_sync(0xFFFFFFFF, v0, 8);
        v0 += __shfl_xor_sync(0xFFFFFFFF, v0, 16);
        v1 += __shfl_xor_sync(0xFFFFFFFF, v1, 4);
        v1 += __shfl_xor_sync(0xFFFFFFFF, v1, 8);
        v1 += __shfl_xor_sync(0xFFFFFFFF, v1, 16);
        if (lane < 4) {
            int col = j0 + n0w + nt * 8 + lane * 2;
            atomicAdd(&g_W[col], v0);
            atomicAdd(&g_W[col + 1], v1);
        }
    }
    __syncthreads();

    // ---- coalesced fp16 store: each warp 16 rows, 256B per row ----
    uint32_t* gS32 = (uint32_t*)g_S;
    #pragma unroll
    for (int it = 0; it < 16; it++) {
        int r = wid * 16 + it;
        #pragma unroll
        for (int h = 0; h < 2; h++) {
            gS32[(size_t)(i0 + r) * (Nn / 2) + (j0 >> 1) + h * 32 + lane] =
                stage[(size_t)r * 68 + h * 32 + lane];
        }
    }
}

__global__ void recip_kernel() {
    int i = blockIdx.x * blockDim.x + threadIdx.x;
    if (i < Nn) { g_rZ[i] = 1.0f / g_Z[i]; g_rW[i] = 1.0f / g_W[i]; }
}

// ---------------- Pass 2: loss from fp16 scores ----------------
__global__ __launch_bounds__(256) void pass2_kernel(const float* __restrict__ label) {
    __shared__ float sred[256];
    const size_t nq = (size_t)Nn * Nn / 8;
    const size_t stride = (size_t)gridDim.x * blockDim.x;
    float acc = 0.f;
    for (size_t q = (size_t)blockIdx.x * blockDim.x + threadIdx.x; q < nq; q += stride) {
        size_t base = q * 8;
        int i = (int)(base >> 13);
        int j = (int)(base & (Nn - 1));
        uint4 sv = *(const uint4*)((const uint32_t*)g_S + (base >> 1));
        float4 l0 = *(const float4*)(label + base);
        float4 l1 = *(const float4*)(label + base + 4);
        float  rZ = g_rZ[i];
        float4 w0 = *(const float4*)&g_rW[j];
        float4 w1 = *(const float4*)&g_rW[j + 4];

        float2 s0 = __half22float2(*(__half2*)&sv.x);
        float2 s1 = __half22float2(*(__half2*)&sv.y);
        float2 s2 = __half22float2(*(__half2*)&sv.z);
        float2 s3 = __half22float2(*(__half2*)&sv.w);

        float e0 = __expf(s0.x), e1 = __expf(s0.y), e2 = __expf(s1.x), e3 = __expf(s1.y);
        float e4 = __expf(s2.x), e5 = __expf(s2.y), e6 = __expf(s3.x), e7 = __expf(s3.y);

        acc += l0.x * (__logf(e0 * rZ + EPSf) + __logf(e0 * w0.x + EPSf));
        acc += l0.y * (__logf(e1 * rZ + EPSf) + __logf(e1 * w0.y + EPSf));
        acc += l0.z * (__logf(e2 * rZ + EPSf) + __logf(e2 * w0.z + EPSf));
        acc += l0.w * (__logf(e3 * rZ + EPSf) + __logf(e3 * w0.w + EPSf));
        acc += l1.x * (__logf(e4 * rZ + EPSf) + __logf(e4 * w1.x + EPSf));
        acc += l1.y * (__logf(e5 * rZ + EPSf) + __logf(e5 * w1.y + EPSf));
        acc += l1.z * (__logf(e6 * rZ + EPSf) + __logf(e6 * w1.z + EPSf));
        acc += l1.w * (__logf(e7 * rZ + EPSf) + __logf(e7 * w1.w + EPSf));
    }
    sred[threadIdx.x] = acc;
    __syncthreads();
    #pragma unroll
    for (int s = 128; s > 0; s >>= 1) {
        if (threadIdx.x < s) sred[threadIdx.x] += sred[threadIdx.x + s];
        __syncthreads();
    }
    if (threadIdx.x == 0) atomicAdd(&g_loss, -(double)sred[0]);
}

__global__ void final_kernel(float* out) { out[0] = (float)g_loss; }

extern "C" void kernel_launch(void* const* d_in, const int* in_sizes, int n_in,
                              void* d_out, int out_size) {
    const float* out1  = (const float*)d_in[0];
    const float* out2  = (const float*)d_in[1];
    const float* label = (const float*)d_in[2];

    cudaFuncSetAttribute(pass1_mma, cudaFuncAttributeMaxDynamicSharedMemorySize, SMEM_BYTES);

    zero_kernel<<<32, 256>>>();
    dim3 grid(Nn / 128, Nn / 128);
    pass1_mma<<<grid, 256, SMEM_BYTES>>>(out1, out2);
    recip_kernel<<<32, 256>>>();
    pass2_kernel<<<8192, 256>>>(label);
    final_kernel<<<1, 1>>>((float*)d_out);
}

// round 6
// speedup vs baseline: 4.2300x; 1.1498x over previous
#include <cuda_runtime.h>
#include <cuda_fp16.h>
#include <cstdint>

#define Nn 8192
#define Mm 128
#define EPSf 1e-4f
#define LDA 136   // fp16 elems per smem tile row (128 + 8 pad -> conflict-free ldmatrix)

// ---------------- device scratch (allocation-free) ----------------
static __device__ __half g_A16[(size_t)Nn * Mm];  // out2 as fp16 (2 MB)
static __device__ __half g_B16[(size_t)Nn * Mm];  // out1 as fp16 (2 MB)
static __device__ float  g_Z[Nn];
static __device__ float  g_W[Nn];
static __device__ float  g_rZ[Nn];
static __device__ float  g_rW[Nn];
static __device__ double g_loss;

__device__ __forceinline__ uint32_t smem_u32(const void* p) {
    uint32_t a;
    asm("{ .reg .u64 t; cvta.to.shared.u64 t, %1; cvt.u32.u64 %0, t; }" : "=r"(a) : "l"(p));
    return a;
}
__device__ __forceinline__ void ldmx4(uint32_t* r, uint32_t addr) {
    asm volatile("ldmatrix.sync.aligned.m8n8.x4.shared.b16 {%0,%1,%2,%3}, [%4];"
                 : "=r"(r[0]), "=r"(r[1]), "=r"(r[2]), "=r"(r[3]) : "r"(addr));
}
__device__ __forceinline__ void mma16816(float* c, const uint32_t* a, uint32_t b0, uint32_t b1) {
    asm volatile(
        "mma.sync.aligned.m16n8k16.row.col.f32.f16.f16.f32 "
        "{%0,%1,%2,%3}, {%4,%5,%6,%7}, {%8,%9}, {%0,%1,%2,%3};"
        : "+f"(c[0]), "+f"(c[1]), "+f"(c[2]), "+f"(c[3])
        : "r"(a[0]), "r"(a[1]), "r"(a[2]), "r"(a[3]), "r"(b0), "r"(b1));
}

__global__ void prep_kernel(const float* __restrict__ out1, const float* __restrict__ out2) {
    int t = blockIdx.x * blockDim.x + threadIdx.x;   // 0 .. 256K-1, 4 floats each
    if (t < Nn * Mm / 4) {
        float4 a = *(const float4*)&out2[(size_t)t * 4];
        float4 b = *(const float4*)&out1[(size_t)t * 4];
        __half2 a0 = __float22half2_rn(make_float2(a.x, a.y));
        __half2 a1 = __float22half2_rn(make_float2(a.z, a.w));
        __half2 b0 = __float22half2_rn(make_float2(b.x, b.y));
        __half2 b1 = __float22half2_rn(make_float2(b.z, b.w));
        *(uint2*)&g_A16[(size_t)t * 4] = make_uint2(*(uint32_t*)&a0, *(uint32_t*)&a1);
        *(uint2*)&g_B16[(size_t)t * 4] = make_uint2(*(uint32_t*)&b0, *(uint32_t*)&b1);
    }
    if (t < Nn) { g_Z[t] = 0.0f; g_W[t] = 0.0f; }
    if (t == 0) g_loss = 0.0;
}

// smem: A, B tiles 128 x LDA fp16 -> 69632 B (2 CTAs/SM)
#define T_ELEMS (128 * LDA)
#define SMEM_BYTES (2 * T_ELEMS * 2)

// shared tile loader: global fp16 (row-major, 128/row) -> padded smem tiles
__device__ __forceinline__ void load_tiles(__half* At, __half* Bt, int i0, int j0, int tid) {
    #pragma unroll 8
    for (int t = tid; t < 2048; t += 256) {
        int row = t >> 4, q = (t & 15) * 8;
        *(uint4*)&At[row * LDA + q] = *(const uint4*)&g_A16[(size_t)(i0 + row) * Mm + q];
        *(uint4*)&Bt[row * LDA + q] = *(const uint4*)&g_B16[(size_t)(j0 + row) * Mm + q];
    }
}

// shared MMA body: computes c[2][8][4] for warp tile 32(m) x 64(n)
__device__ __forceinline__ void mma_tile(const __half* At, const __half* Bt,
                                         int m0w, int n0w, int lane, float c[2][8][4]) {
    const int aro = (lane & 7) + ((lane >> 3) & 1) * 8;
    const int ako = ((lane >> 4) & 1) * 8;
    const int bro = (lane & 7) + ((lane >> 4) & 1) * 8;
    const int bko = ((lane >> 3) & 1) * 8;

    const uint32_t sA = smem_u32(At), sB = smem_u32(Bt);
    const uint32_t aoff = (uint32_t)(((m0w + aro) * LDA + ako) * 2);
    uint32_t boff[4];
    #pragma unroll
    for (int p = 0; p < 4; p++)
        boff[p] = (uint32_t)(((n0w + p * 16 + bro) * LDA + bko) * 2);

    #pragma unroll
    for (int kk = 0; kk < 8; kk++) {
        const uint32_t kb = (uint32_t)(kk * 32);
        uint32_t av[2][4], bv[4][4];
        #pragma unroll
        for (int mt = 0; mt < 2; mt++)
            ldmx4(av[mt], sA + aoff + (uint32_t)(mt * 16 * LDA * 2) + kb);
        #pragma unroll
        for (int p = 0; p < 4; p++)
            ldmx4(bv[p], sB + boff[p] + kb);
        #pragma unroll
        for (int mt = 0; mt < 2; mt++)
            #pragma unroll
            for (int nt = 0; nt < 8; nt++) {
                const int p = nt >> 1, r = (nt & 1) * 2;
                mma16816(c[mt][nt], av[mt], bv[p][r], bv[p][r + 1]);
            }
    }
}

// ---------------- Pass 1: GEMM -> exp -> row/col sums (no S store) ----------------
__global__ __launch_bounds__(256, 2) void pass1_sums() {
    extern __shared__ char sm[];
    __half* At = (__half*)sm;
    __half* Bt = At + T_ELEMS;

    const int tid = threadIdx.x, wid = tid >> 5, lane = tid & 31;
    const int i0 = blockIdx.y * 128, j0 = blockIdx.x * 128;
    const int wm = wid & 3, wn = wid >> 2;
    const int m0w = wm * 32, n0w = wn * 64;

    load_tiles(At, Bt, i0, j0, tid);
    __syncthreads();

    float c[2][8][4];
    #pragma unroll
    for (int mt = 0; mt < 2; mt++)
        #pragma unroll
        for (int nt = 0; nt < 8; nt++)
            #pragma unroll
            for (int q = 0; q < 4; q++) c[mt][nt][q] = 0.f;

    mma_tile(At, Bt, m0w, n0w, lane, c);

    // exp in registers
    #pragma unroll
    for (int mt = 0; mt < 2; mt++)
        #pragma unroll
        for (int nt = 0; nt < 8; nt++)
            #pragma unroll
            for (int q = 0; q < 4; q++) c[mt][nt][q] = __expf(c[mt][nt][q]);

    // row sums (quad shuffle) + atomics
    #pragma unroll
    for (int mt = 0; mt < 2; mt++) {
        float r0 = 0.f, r1 = 0.f;
        #pragma unroll
        for (int nt = 0; nt < 8; nt++) {
            r0 += c[mt][nt][0] + c[mt][nt][1];
            r1 += c[mt][nt][2] + c[mt][nt][3];
        }
        r0 += __shfl_xor_sync(0xFFFFFFFF, r0, 1);
        r0 += __shfl_xor_sync(0xFFFFFFFF, r0, 2);
        r1 += __shfl_xor_sync(0xFFFFFFFF, r1, 1);
        r1 += __shfl_xor_sync(0xFFFFFFFF, r1, 2);
        if ((lane & 3) == 0) {
            atomicAdd(&g_Z[i0 + m0w + mt * 16 + (lane >> 2)], r0);
            atomicAdd(&g_Z[i0 + m0w + mt * 16 + 8 + (lane >> 2)], r1);
        }
    }
    // col sums (cross-quad shuffle) + atomics
    #pragma unroll
    for (int nt = 0; nt < 8; nt++) {
        float v0 = c[0][nt][0] + c[0][nt][2] + c[1][nt][0] + c[1][nt][2];
        float v1 = c[0][nt][1] + c[0][nt][3] + c[1][nt][1] + c[1][nt][3];
        v0 += __shfl_xor_sync(0xFFFFFFFF, v0, 4);
        v0 += __shfl_xor_sync(0xFFFFFFFF, v0, 8);
        v0 += __shfl_xor_sync(0xFFFFFFFF, v0, 16);
        v1 += __shfl_xor_sync(0xFFFFFFFF, v1, 4);
        v1 += __shfl_xor_sync(0xFFFFFFFF, v1, 8);
        v1 += __shfl_xor_sync(0xFFFFFFFF, v1, 16);
        if (lane < 4) {
            int col = j0 + n0w + nt * 8 + lane * 2;
            atomicAdd(&g_W[col], v0);
            atomicAdd(&g_W[col + 1], v1);
        }
    }
}

__global__ void recip_kernel() {
    int i = blockIdx.x * blockDim.x + threadIdx.x;
    if (i < Nn) { g_rZ[i] = 1.0f / g_Z[i]; g_rW[i] = 1.0f / g_W[i]; }
}

// ---------------- Pass 2: recompute GEMM, fused loss ----------------
__global__ __launch_bounds__(256, 2) void pass2_fused(const float* __restrict__ label) {
    extern __shared__ char sm[];
    __half* At = (__half*)sm;
    __half* Bt = At + T_ELEMS;

    const int tid = threadIdx.x, wid = tid >> 5, lane = tid & 31;
    const int i0 = blockIdx.y * 128, j0 = blockIdx.x * 128;
    const int wm = wid & 3, wn = wid >> 2;
    const int m0w = wm * 32, n0w = wn * 64;

    load_tiles(At, Bt, i0, j0, tid);
    __syncthreads();

    float c[2][8][4];
    #pragma unroll
    for (int mt = 0; mt < 2; mt++)
        #pragma unroll
        for (int nt = 0; nt < 8; nt++)
            #pragma unroll
            for (int q = 0; q < 4; q++) c[mt][nt][q] = 0.f;

    mma_tile(At, Bt, m0w, n0w, lane, c);

    // consume fragments: loss += label * log((e*rZ+eps)*(e*rW+eps))
    float acc = 0.f;
    #pragma unroll
    for (int mt = 0; mt < 2; mt++) {
        const int r0i = i0 + m0w + mt * 16 + (lane >> 2);
        const float rZ0 = g_rZ[r0i], rZ8 = g_rZ[r0i + 8];
        #pragma unroll
        for (int nt = 0; nt < 8; nt++) {
            const int col = j0 + n0w + nt * 8 + (lane & 3) * 2;
            const float rw0 = g_rW[col], rw1 = g_rW[col + 1];
            float2 l0 = *(const float2*)&label[(size_t)r0i * Nn + col];
            float2 l1 = *(const float2*)&label[(size_t)(r0i + 8) * Nn + col];

            float e0 = __expf(c[mt][nt][0]);
            float e1 = __expf(c[mt][nt][1]);
            float e2 = __expf(c[mt][nt][2]);
            float e3 = __expf(c[mt][nt][3]);

            acc += l0.x * __logf(fmaf(e0, rZ0, EPSf) * fmaf(e0, rw0, EPSf));
            acc += l0.y * __logf(fmaf(e1, rZ0, EPSf) * fmaf(e1, rw1, EPSf));
            acc += l1.x * __logf(fmaf(e2, rZ8, EPSf) * fmaf(e2, rw0, EPSf));
            acc += l1.y * __logf(fmaf(e3, rZ8, EPSf) * fmaf(e3, rw1, EPSf));
        }
    }

    // block reduction (reuse smem after tiles are dead)
    __syncthreads();
    float* red = (float*)sm;
    acc += __shfl_xor_sync(0xFFFFFFFF, acc, 16);
    acc += __shfl_xor_sync(0xFFFFFFFF, acc, 8);
    acc += __shfl_xor_sync(0xFFFFFFFF, acc, 4);
    acc += __shfl_xor_sync(0xFFFFFFFF, acc, 2);
    acc += __shfl_xor_sync(0xFFFFFFFF, acc, 1);
    if (lane == 0) red[wid] = acc;
    __syncthreads();
    if (tid == 0) {
        float s = 0.f;
        #pragma unroll
        for (int w = 0; w < 8; w++) s += red[w];
        atomicAdd(&g_loss, -(double)s);
    }
}

__global__ void final_kernel(float* out) { out[0] = (float)g_loss; }

extern "C" void kernel_launch(void* const* d_in, const int* in_sizes, int n_in,
                              void* d_out, int out_size) {
    const float* out1  = (const float*)d_in[0];
    const float* out2  = (const float*)d_in[1];
    const float* label = (const float*)d_in[2];

    cudaFuncSetAttribute(pass1_sums, cudaFuncAttributeMaxDynamicSharedMemorySize, SMEM_BYTES);
    cudaFuncSetAttribute(pass2_fused, cudaFuncAttributeMaxDynamicSharedMemorySize, SMEM_BYTES);

    prep_kernel<<<(Nn * Mm / 4 + 255) / 256, 256>>>(out1, out2);
    dim3 grid(Nn / 128, Nn / 128);
    pass1_sums<<<grid, 256, SMEM_BYTES>>>();
    recip_kernel<<<32, 256>>>();
    pass2_fused<<<grid, 256, SMEM_BYTES>>>(label);
    final_kernel<<<1, 1>>>((float*)d_out);
}